// round 4
// baseline (speedup 1.0000x reference)
#include <cuda_runtime.h>

#define TPB 256

// Scratch: level 0 (d, later inclusive scan S0) + tile-sum pyramid (factor 16).
__device__ __align__(16) float g_buf[13000000];
__device__ double g_thr_part[65536];
__device__ double g_win_part[65536];

__device__ __forceinline__ float edge_len(float2 a, float2 b) {
    float dx = __fsub_rn(a.x, b.x);
    float dy = __fsub_rn(a.y, b.y);
    float s  = __fmaf_rn(dy, dy, __fmul_rn(dx, dx));
    return __fsqrt_rn(s);
}

__global__ void edges_kernel(const float2* __restrict__ pts,
                             const int* __restrict__ faces, int F) {
    int f = blockIdx.x * blockDim.x + threadIdx.x;
    double acc = 0.0;
    if (f < F) {
        int b = 3 * f;
        int i0 = faces[b], i1 = faces[b + 1], i2 = faces[b + 2];
        float2 p0 = pts[i0], p1 = pts[i1], p2 = pts[i2];
        float d0 = edge_len(p2, p0);
        float d1 = edge_len(p0, p1);
        float d2 = edge_len(p1, p2);
        g_buf[b]     = d0;
        g_buf[b + 1] = d1;
        g_buf[b + 2] = d2;
        if (d0 < 7.0f) { float s = __fsub_rn(7.0f, d0); acc += (double)__fmul_rn(s, s); }
        if (d1 < 7.0f) { float s = __fsub_rn(7.0f, d1); acc += (double)__fmul_rn(s, s); }
        if (d2 < 7.0f) { float s = __fsub_rn(7.0f, d2); acc += (double)__fmul_rn(s, s); }
    }
    __shared__ double sh[TPB];
    sh[threadIdx.x] = acc;
    __syncthreads();
    for (int o = TPB / 2; o > 0; o >>= 1) {
        if (threadIdx.x < o) sh[threadIdx.x] += sh[threadIdx.x + o];
        __syncthreads();
    }
    if (threadIdx.x == 0) g_thr_part[blockIdx.x] = sh[0];
}

// XLA ReduceWindowRewriter emulation, base length 16.
// Downsweep: tile_sum[t] = ((((0 + x[16t]) + x[16t+1]) + ...) sequential RN adds,
// exactly the last column of the naive inner reduce_window (zero padding is inert).
__global__ void tilesum_kernel(long src_off, long dst_off, int n, int tiles) {
    int t = blockIdx.x * blockDim.x + threadIdx.x;
    if (t >= tiles) return;
    int base = t * 16;
    int lim = n - base; if (lim > 16) lim = 16;
    float acc = 0.0f;
    #pragma unroll
    for (int i = 0; i < 16; i++) {
        if (i < lim) acc = __fadd_rn(acc, g_buf[src_off + base + i]);
    }
    g_buf[dst_off + t] = acc;
}

// Top level (n <= 16): naive sequential inclusive scan in place.
__global__ void seqscan_kernel(long off, int n) {
    float acc = 0.0f;
    for (int i = 0; i < n; i++) {
        acc = __fadd_rn(acc, g_buf[off + i]);
        g_buf[off + i] = acc;
    }
}

// Upsweep: S_l[16t+i] = RN( S_{l+1}[t-1] + seq_prefix_i )  (offset 0 for t=0).
// In place over A_l; each thread owns its 16 elements (read-then-write, no races).
__global__ void up_kernel(long a_off, long s_off, int n, int tiles) {
    int t = blockIdx.x * blockDim.x + threadIdx.x;
    if (t >= tiles) return;
    float off = (t > 0) ? g_buf[s_off + t - 1] : 0.0f;
    int base = t * 16;
    int lim = n - base; if (lim > 16) lim = 16;
    float acc = 0.0f;
    #pragma unroll
    for (int i = 0; i < 16; i++) {
        if (i < lim) {
            acc = __fadd_rn(acc, g_buf[a_off + base + i]);
            g_buf[a_off + base + i] = __fadd_rn(off, acc);
        }
    }
}

// g_buf[0..M) now holds the inclusive cumsum S0; cs[k] = S0[k-1], cs[0] = 0.
__global__ void window_kernel(int Mj) {
    int j = blockIdx.x * blockDim.x + threadIdx.x;
    double acc = 0.0;
    if (j < Mj) {
        float sj = g_buf[j];
        float sn = g_buf[j + 5];
        float lo = (j >= 5) ? g_buf[j - 5] : 0.0f;
        int cnt = (j + 1 < 5) ? (j + 1) : 5;
        float avg_prev = __fdiv_rn(__fsub_rn(sj, lo), (float)cnt);
        float avg_next = __fdiv_rn(__fsub_rn(sn, sj), 5.0f);
        float diff = fabsf(__fsub_rn(avg_next, avg_prev));
        acc = (double)expf(diff);
    }
    __shared__ double sh[TPB];
    sh[threadIdx.x] = acc;
    __syncthreads();
    for (int o = TPB / 2; o > 0; o >>= 1) {
        if (threadIdx.x < o) sh[threadIdx.x] += sh[threadIdx.x + o];
        __syncthreads();
    }
    if (threadIdx.x == 0) g_win_part[blockIdx.x] = sh[0];
}

__global__ void final_kernel(int np_thr, int np_win, float* __restrict__ out) {
    int tid = threadIdx.x;
    double s = 0.0;
    for (int i = tid; i < np_thr; i += 256) s += g_thr_part[i];
    for (int i = tid; i < np_win; i += 256) s += g_win_part[i];
    __shared__ double sh[256];
    sh[tid] = s;
    __syncthreads();
    for (int o = 128; o > 0; o >>= 1) {
        if (tid < o) sh[tid] += sh[tid + o];
        __syncthreads();
    }
    if (tid == 0) out[0] = (float)sh[0];
}

extern "C" void kernel_launch(void* const* d_in, const int* in_sizes, int n_in,
                              void* d_out, int out_size) {
    const float2* pts = (const float2*)d_in[0];
    const int* faces = (const int*)d_in[1];
    int M = in_sizes[1];      // 3 * F
    int F = M / 3;

    int nb_f = (F + TPB - 1) / TPB;
    edges_kernel<<<nb_f, TPB>>>(pts, faces, F);

    // Level structure: ns[l+1] = ceil(ns[l]/16) until n <= 16.
    int ns[12];
    long offs[12];
    ns[0] = M; offs[0] = 0;
    int L = 0;
    while (ns[L] > 16) {
        ns[L + 1] = (ns[L] + 15) / 16;
        offs[L + 1] = offs[L] + ns[L];
        L++;
    }

    for (int l = 0; l < L; l++) {
        int tiles = ns[l + 1];
        tilesum_kernel<<<(tiles + TPB - 1) / TPB, TPB>>>(offs[l], offs[l + 1], ns[l], tiles);
    }

    seqscan_kernel<<<1, 1>>>(offs[L], ns[L]);

    for (int l = L - 1; l >= 0; l--) {
        int tiles = ns[l + 1];
        up_kernel<<<(tiles + TPB - 1) / TPB, TPB>>>(offs[l], offs[l + 1], ns[l], tiles);
    }

    int Mj = M - 5;
    int nb_w = (Mj + TPB - 1) / TPB;
    window_kernel<<<nb_w, TPB>>>(Mj);

    final_kernel<<<1, 256>>>(nb_f, nb_w, (float*)d_out);
}

// round 5
// speedup vs baseline: 1.9784x; 1.9784x over previous
#include <cuda_runtime.h>

#define TPB 256

// d values (level 0)
__device__ __align__(16) float g_d[12000032];
// tile-sum pyramid: lvl1 (ceil(M/16)) and above
__device__ __align__(16) float g_lvl[900032];
__device__ double g_thr_part[65536];
__device__ double g_win_part[65536];

__device__ __forceinline__ int sidx(int i) { return i + (i >> 4); }  // 17-stride pad

__device__ __forceinline__ float edge_len(float2 a, float2 b) {
    float dx = __fsub_rn(a.x, b.x);
    float dy = __fsub_rn(a.y, b.y);
    float s  = __fmaf_rn(dy, dy, __fmul_rn(dx, dx));
    return __fsqrt_rn(s);
}

// Kernel A: edges + threshold partial + level-0 tile sums (48 tiles per block).
// Block = 256 faces = 768 d values (block d-range is 16-aligned: 768 = 48*16).
__global__ void edges_kernel(const float2* __restrict__ pts,
                             const int* __restrict__ faces, int F, int M) {
    __shared__ float sd[816];          // 768 + 48 pad
    __shared__ double sh[TPB];
    int tid = threadIdx.x;
    int f = blockIdx.x * TPB + tid;
    double acc = 0.0;
    if (f < F) {
        int b = 3 * f;
        int i0 = faces[b], i1 = faces[b + 1], i2 = faces[b + 2];
        float2 p0 = __ldg(&pts[i0]), p1 = __ldg(&pts[i1]), p2 = __ldg(&pts[i2]);
        float d0 = edge_len(p2, p0);
        float d1 = edge_len(p0, p1);
        float d2 = edge_len(p1, p2);
        g_d[b] = d0; g_d[b + 1] = d1; g_d[b + 2] = d2;
        int lb = 3 * tid;
        sd[sidx(lb)] = d0; sd[sidx(lb + 1)] = d1; sd[sidx(lb + 2)] = d2;
        if (d0 < 7.0f) { float s = __fsub_rn(7.0f, d0); acc += (double)__fmul_rn(s, s); }
        if (d1 < 7.0f) { float s = __fsub_rn(7.0f, d1); acc += (double)__fmul_rn(s, s); }
        if (d2 < 7.0f) { float s = __fsub_rn(7.0f, d2); acc += (double)__fmul_rn(s, s); }
    }
    __syncthreads();
    // Level-0 tile sums: sequential RN adds in index order (bitwise = reduce_window inner scan tail).
    if (tid < 48) {
        int gbase = blockIdx.x * 768;          // block's global d base (16-aligned)
        int lim = M - gbase;                   // valid d count in this block
        float a = 0.0f;
        int lb = tid * 16;
        #pragma unroll
        for (int i = 0; i < 16; i++) {
            if (lb + i < lim) a = __fadd_rn(a, sd[sidx(lb + i)]);
        }
        int gt = blockIdx.x * 48 + tid;
        if (lb < lim) g_lvl[gt] = a;
    }
    sh[tid] = acc;
    __syncthreads();
    for (int o = TPB / 2; o > 0; o >>= 1) {
        if (tid < o) sh[tid] += sh[tid + o];
        __syncthreads();
    }
    if (tid == 0) g_thr_part[blockIdx.x] = sh[0];
}

// Mid-pyramid downsweep: tile_sum over g_lvl (sequential RN adds from 0).
__global__ void tilesum_kernel(long src_off, long dst_off, int n, int tiles) {
    int t = blockIdx.x * blockDim.x + threadIdx.x;
    if (t >= tiles) return;
    int base = t * 16;
    int lim = n - base; if (lim > 16) lim = 16;
    float acc = 0.0f;
    #pragma unroll
    for (int i = 0; i < 16; i++) {
        if (i < lim) acc = __fadd_rn(acc, g_lvl[src_off + base + i]);
    }
    g_lvl[dst_off + t] = acc;
}

__global__ void seqscan_kernel(long off, int n) {
    float acc = 0.0f;
    for (int i = 0; i < n; i++) {
        acc = __fadd_rn(acc, g_lvl[off + i]);
        g_lvl[off + i] = acc;
    }
}

// Mid-pyramid upsweep (in place): S_l[16t+i] = RN(S_{l+1}[t-1] + seq_prefix_i)
__global__ void up_kernel(long a_off, long s_off, int n, int tiles) {
    int t = blockIdx.x * blockDim.x + threadIdx.x;
    if (t >= tiles) return;
    float off = (t > 0) ? g_lvl[s_off + t - 1] : 0.0f;
    int base = t * 16;
    int lim = n - base; if (lim > 16) lim = 16;
    float acc = 0.0f;
    #pragma unroll
    for (int i = 0; i < 16; i++) {
        if (i < lim) {
            acc = __fadd_rn(acc, g_lvl[a_off + base + i]);
            g_lvl[a_off + base + i] = __fadd_rn(off, acc);
        }
    }
}

// Kernel B: reconstruct S0 per tile from d + S1 (bitwise = old L0 upsweep), then windows.
// Block = 256 tiles = 4096 j values; halo tile on each side.
__global__ void window_kernel(int M, int Mj, int nTiles) {
    __shared__ float s[4448];          // sidx(258*16-1)+1 = 4127+257+1 -> 4385; rounded up
    __shared__ double sh[TPB];
    int tid = threadIdx.x;
    int T0 = blockIdx.x * TPB;
    int dstart = 16 * (T0 - 1);        // global d index of local idx 0
    // Coalesced load of d slice [dstart, dstart + 4128)
    for (int idx = tid; idx < 258 * 16; idx += TPB) {
        int g = dstart + idx;
        float v = (g >= 0 && g < M) ? g_d[g] : 0.0f;
        s[sidx(idx)] = v;
    }
    __syncthreads();
    // Reconstruct S0 in place: local tile lt <-> global tile T0-1+lt
    for (int lt = tid; lt < 258; lt += TPB) {
        int gt = T0 - 1 + lt;
        if (gt >= 0 && gt < nTiles) {
            float off = (gt > 0) ? g_lvl[gt - 1] : 0.0f;
            float a = 0.0f;
            int lb = lt * 16;
            #pragma unroll
            for (int i = 0; i < 16; i++) {
                int p = sidx(lb + i);
                a = __fadd_rn(a, s[p]);
                s[p] = __fadd_rn(off, a);
            }
        }
    }
    __syncthreads();
    // Windows: thread handles global tile T0 + tid (local tile tid+1)
    double acc = 0.0;
    int gt = T0 + tid;
    if (gt < nTiles) {
        int lb = (tid + 1) * 16;
        #pragma unroll
        for (int i = 0; i < 16; i++) {
            int j = gt * 16 + i;
            if (j < Mj) {
                int lj = lb + i;
                float sj = s[sidx(lj)];
                float sn = s[sidx(lj + 5)];
                float lo = (j >= 5) ? s[sidx(lj - 5)] : 0.0f;
                int cnt = (j + 1 < 5) ? (j + 1) : 5;
                float avg_prev = __fdiv_rn(__fsub_rn(sj, lo), (float)cnt);
                float avg_next = __fdiv_rn(__fsub_rn(sn, sj), 5.0f);
                float diff = fabsf(__fsub_rn(avg_next, avg_prev));
                acc += (double)expf(diff);
            }
        }
    }
    sh[tid] = acc;
    __syncthreads();
    for (int o = TPB / 2; o > 0; o >>= 1) {
        if (tid < o) sh[tid] += sh[tid + o];
        __syncthreads();
    }
    if (tid == 0) g_win_part[blockIdx.x] = sh[0];
}

__global__ void final_kernel(int np_thr, int np_win, float* __restrict__ out) {
    int tid = threadIdx.x;
    double s = 0.0;
    for (int i = tid; i < np_thr; i += 256) s += g_thr_part[i];
    for (int i = tid; i < np_win; i += 256) s += g_win_part[i];
    __shared__ double sh[256];
    sh[tid] = s;
    __syncthreads();
    for (int o = 128; o > 0; o >>= 1) {
        if (tid < o) sh[tid] += sh[tid + o];
        __syncthreads();
    }
    if (tid == 0) out[0] = (float)sh[0];
}

extern "C" void kernel_launch(void* const* d_in, const int* in_sizes, int n_in,
                              void* d_out, int out_size) {
    const float2* pts = (const float2*)d_in[0];
    const int* faces = (const int*)d_in[1];
    int M = in_sizes[1];      // 3 * F
    int F = M / 3;

    int nb_f = (F + TPB - 1) / TPB;
    edges_kernel<<<nb_f, TPB>>>(pts, faces, F, M);

    // Pyramid levels over g_lvl: ns[1] = ceil(M/16), ns[l+1] = ceil(ns[l]/16)
    int ns[12];
    long offs[12];
    ns[1] = (M + 15) / 16;
    offs[1] = 0;
    int L = 1;
    while (ns[L] > 16) {
        ns[L + 1] = (ns[L] + 15) / 16;
        offs[L + 1] = offs[L] + ns[L];
        L++;
    }

    for (int l = 1; l < L; l++) {
        int tiles = ns[l + 1];
        tilesum_kernel<<<(tiles + TPB - 1) / TPB, TPB>>>(offs[l], offs[l + 1], ns[l], tiles);
    }

    seqscan_kernel<<<1, 1>>>(offs[L], ns[L]);

    for (int l = L - 1; l >= 1; l--) {
        int tiles = ns[l + 1];
        up_kernel<<<(tiles + TPB - 1) / TPB, TPB>>>(offs[l], offs[l + 1], ns[l], tiles);
    }

    int Mj = M - 5;
    int nTiles = ns[1];
    int nb_w = (nTiles + TPB - 1) / TPB;
    window_kernel<<<nb_w, TPB>>>(M, Mj, nTiles);

    final_kernel<<<1, 256>>>(nb_f, nb_w, (float*)d_out);
}

// round 6
// speedup vs baseline: 2.4248x; 1.2256x over previous
#include <cuda_runtime.h>

#define TPB 256

// d values (level 0)
__device__ __align__(16) float g_d[12000032];
// pyramid: A1/S1 at [0, n1), A2/S2 at [n1, n1+n2)
__device__ __align__(16) float g_lvl[900032];
__device__ double g_thr_part[65536];
__device__ double g_win_part[65536];

__device__ __forceinline__ int sidx(int i) { return i + (i >> 4); }  // 17-stride pad

__device__ __forceinline__ float edge_len(float2 a, float2 b) {
    float dx = __fsub_rn(a.x, b.x);
    float dy = __fsub_rn(a.y, b.y);
    float s  = __fmaf_rn(dy, dy, __fmul_rn(dx, dx));
    return __fsqrt_rn(s);
}

// Kernel A: edges + threshold partial + A1 (48/block) + A2 (3/block).
// Block = 256 faces = 768 d values; 768 = 48*16, 48 = 3*16 (both tile-aligned).
__global__ void edges_kernel(const float2* __restrict__ pts,
                             const int* __restrict__ faces, int F, int M,
                             long off2, int n1, int n2) {
    __shared__ float sd[816];          // 768 + 48 pad
    __shared__ float sA1[48];
    __shared__ double sh[TPB];
    int tid = threadIdx.x;
    int f = blockIdx.x * TPB + tid;
    float facc = 0.0f;
    if (f < F) {
        int b = 3 * f;
        int i0 = faces[b], i1 = faces[b + 1], i2 = faces[b + 2];
        float2 p0 = __ldg(&pts[i0]), p1 = __ldg(&pts[i1]), p2 = __ldg(&pts[i2]);
        float d0 = edge_len(p2, p0);
        float d1 = edge_len(p0, p1);
        float d2 = edge_len(p1, p2);
        g_d[b] = d0; g_d[b + 1] = d1; g_d[b + 2] = d2;
        int lb = 3 * tid;
        sd[sidx(lb)] = d0; sd[sidx(lb + 1)] = d1; sd[sidx(lb + 2)] = d2;
        if (d0 < 7.0f) { float s = __fsub_rn(7.0f, d0); facc += __fmul_rn(s, s); }
        if (d1 < 7.0f) { float s = __fsub_rn(7.0f, d1); facc += __fmul_rn(s, s); }
        if (d2 < 7.0f) { float s = __fsub_rn(7.0f, d2); facc += __fmul_rn(s, s); }
    }
    __syncthreads();
    int gbase = blockIdx.x * 768;              // block's global d base (16-aligned)
    int lim = M - gbase;                       // valid d count in this block
    if (tid < 48) {
        // A1 tile sums: sequential RN adds in index order.
        float a = 0.0f;
        int lb = tid * 16;
        #pragma unroll
        for (int i = 0; i < 16; i++) {
            if (lb + i < lim) a = __fadd_rn(a, sd[sidx(lb + i)]);
        }
        sA1[tid] = a;
        int gt = blockIdx.x * 48 + tid;
        if (lb < lim && gt < n1) g_lvl[gt] = a;
    }
    __syncthreads();
    if (tid < 3) {
        // A2 entries: sequential RN sums of 16 A1 entries (only existing ones).
        int gt2 = blockIdx.x * 3 + tid;
        if (gt2 < n2) {
            int a1base = blockIdx.x * 48 + tid * 16;   // global A1 base of this A2 tile
            float a = 0.0f;
            #pragma unroll
            for (int i = 0; i < 16; i++) {
                if (a1base + i < n1) a = __fadd_rn(a, sA1[tid * 16 + i]);
            }
            if (a1base < n1) g_lvl[off2 + gt2] = a;
        }
    }
    sh[tid] = (double)facc;
    __syncthreads();
    for (int o = TPB / 2; o > 0; o >>= 1) {
        if (tid < o) sh[tid] += sh[tid + o];
        __syncthreads();
    }
    if (tid == 0) g_thr_part[blockIdx.x] = sh[0];
}

// Single-block kernel: A2 (gmem, n2) -> A3 -> A4 -> A5 (smem) -> seq scan ->
// S4 -> S3 -> S2 (gmem in place). Exact same add sequences as the per-level kernels.
__global__ void fused_mid(long off2, int n2) {
    __shared__ float sA3[3072];
    __shared__ float sA4[256];
    __shared__ float sA5[16];
    int tid = threadIdx.x, nt = blockDim.x;
    int n3 = (n2 + 15) / 16;
    int n4 = (n3 + 15) / 16;
    int n5 = (n4 + 15) / 16;
    // A3
    for (int t = tid; t < n3; t += nt) {
        float a = 0.0f;
        int base = t * 16, l = n2 - base; if (l > 16) l = 16;
        #pragma unroll
        for (int i = 0; i < 16; i++) if (i < l) a = __fadd_rn(a, g_lvl[off2 + base + i]);
        sA3[t] = a;
    }
    __syncthreads();
    // A4
    for (int t = tid; t < n4; t += nt) {
        float a = 0.0f;
        int base = t * 16, l = n3 - base; if (l > 16) l = 16;
        #pragma unroll
        for (int i = 0; i < 16; i++) if (i < l) a = __fadd_rn(a, sA3[base + i]);
        sA4[t] = a;
    }
    __syncthreads();
    // A5
    for (int t = tid; t < n5; t += nt) {
        float a = 0.0f;
        int base = t * 16, l = n4 - base; if (l > 16) l = 16;
        #pragma unroll
        for (int i = 0; i < 16; i++) if (i < l) a = __fadd_rn(a, sA4[base + i]);
        sA5[t] = a;
    }
    __syncthreads();
    // sequential scan of top level (n5 <= 16)
    if (tid == 0) {
        float acc = 0.0f;
        for (int i = 0; i < n5; i++) { acc = __fadd_rn(acc, sA5[i]); sA5[i] = acc; }
    }
    __syncthreads();
    // S4 = up(A4, S5)
    for (int t = tid; t < n5; t += nt) {
        float off = (t > 0) ? sA5[t - 1] : 0.0f;
        int base = t * 16, l = n4 - base; if (l > 16) l = 16;
        float acc = 0.0f;
        #pragma unroll
        for (int i = 0; i < 16; i++) if (i < l) {
            acc = __fadd_rn(acc, sA4[base + i]);
            sA4[base + i] = __fadd_rn(off, acc);
        }
    }
    __syncthreads();
    // S3 = up(A3, S4)
    for (int t = tid; t < n4; t += nt) {
        float off = (t > 0) ? sA4[t - 1] : 0.0f;
        int base = t * 16, l = n3 - base; if (l > 16) l = 16;
        float acc = 0.0f;
        #pragma unroll
        for (int i = 0; i < 16; i++) if (i < l) {
            acc = __fadd_rn(acc, sA3[base + i]);
            sA3[base + i] = __fadd_rn(off, acc);
        }
    }
    __syncthreads();
    // S2 = up(A2, S3), gmem in place
    for (int t = tid; t < n3; t += nt) {
        float off = (t > 0) ? sA3[t - 1] : 0.0f;
        int base = t * 16, l = n2 - base; if (l > 16) l = 16;
        float acc = 0.0f;
        #pragma unroll
        for (int i = 0; i < 16; i++) if (i < l) {
            acc = __fadd_rn(acc, g_lvl[off2 + base + i]);
            g_lvl[off2 + base + i] = __fadd_rn(off, acc);
        }
    }
}

// up1: S1[16t+i] = RN(S2[t-1] + prefix(A1)), A1 region in place.
__global__ void up1_kernel(long off2, int n1, int tiles) {
    int t = blockIdx.x * blockDim.x + threadIdx.x;
    if (t >= tiles) return;
    float off = (t > 0) ? g_lvl[off2 + t - 1] : 0.0f;
    int base = t * 16;
    int lim = n1 - base; if (lim > 16) lim = 16;
    float acc = 0.0f;
    #pragma unroll
    for (int i = 0; i < 16; i++) {
        if (i < lim) {
            acc = __fadd_rn(acc, g_lvl[base + i]);
            g_lvl[base + i] = __fadd_rn(off, acc);
        }
    }
}

// Kernel B: reconstruct S0 per tile from d + S1 (bitwise = L0 upsweep), then windows.
__global__ void window_kernel(int M, int Mj, int nTiles) {
    __shared__ float s[4448];
    __shared__ double sh[TPB];
    int tid = threadIdx.x;
    int T0 = blockIdx.x * TPB;
    int dstart = 16 * (T0 - 1);
    for (int idx = tid; idx < 258 * 16; idx += TPB) {
        int g = dstart + idx;
        float v = (g >= 0 && g < M) ? g_d[g] : 0.0f;
        s[sidx(idx)] = v;
    }
    __syncthreads();
    for (int lt = tid; lt < 258; lt += TPB) {
        int gt = T0 - 1 + lt;
        if (gt >= 0 && gt < nTiles) {
            float off = (gt > 0) ? g_lvl[gt - 1] : 0.0f;
            float a = 0.0f;
            int lb = lt * 16;
            #pragma unroll
            for (int i = 0; i < 16; i++) {
                int p = sidx(lb + i);
                a = __fadd_rn(a, s[p]);
                s[p] = __fadd_rn(off, a);
            }
        }
    }
    __syncthreads();
    float facc = 0.0f;
    int gt = T0 + tid;
    if (gt < nTiles) {
        int lb = (tid + 1) * 16;
        #pragma unroll
        for (int i = 0; i < 16; i++) {
            int j = gt * 16 + i;
            if (j < Mj) {
                int lj = lb + i;
                float sj = s[sidx(lj)];
                float sn = s[sidx(lj + 5)];
                float lo = (j >= 5) ? s[sidx(lj - 5)] : 0.0f;
                float a = __fsub_rn(sj, lo);
                float b = __fsub_rn(sn, sj);
                float avg_prev;
                if (j >= 4) avg_prev = __fmul_rn(a, 0.2f);
                else        avg_prev = __fdiv_rn(a, (float)(j + 1));
                float avg_next = __fmul_rn(b, 0.2f);
                float diff = fabsf(__fsub_rn(avg_next, avg_prev));
                facc += __expf(diff);
            }
        }
    }
    sh[tid] = (double)facc;
    __syncthreads();
    for (int o = TPB / 2; o > 0; o >>= 1) {
        if (tid < o) sh[tid] += sh[tid + o];
        __syncthreads();
    }
    if (tid == 0) g_win_part[blockIdx.x] = sh[0];
}

__global__ void final_kernel(int np_thr, int np_win, float* __restrict__ out) {
    int tid = threadIdx.x;
    double s = 0.0;
    for (int i = tid; i < np_thr; i += 256) s += g_thr_part[i];
    for (int i = tid; i < np_win; i += 256) s += g_win_part[i];
    __shared__ double sh[256];
    sh[tid] = s;
    __syncthreads();
    for (int o = 128; o > 0; o >>= 1) {
        if (tid < o) sh[tid] += sh[tid + o];
        __syncthreads();
    }
    if (tid == 0) out[0] = (float)sh[0];
}

extern "C" void kernel_launch(void* const* d_in, const int* in_sizes, int n_in,
                              void* d_out, int out_size) {
    const float2* pts = (const float2*)d_in[0];
    const int* faces = (const int*)d_in[1];
    int M = in_sizes[1];      // 3 * F
    int F = M / 3;

    int n1 = (M + 15) / 16;
    int n2 = (n1 + 15) / 16;
    long off2 = n1;

    int nb_f = (F + TPB - 1) / TPB;
    edges_kernel<<<nb_f, TPB>>>(pts, faces, F, M, off2, n1, n2);

    fused_mid<<<1, 1024>>>(off2, n2);

    up1_kernel<<<(n2 + TPB - 1) / TPB, TPB>>>(off2, n1, n2);

    int Mj = M - 5;
    int nb_w = (n1 + TPB - 1) / TPB;
    window_kernel<<<nb_w, TPB>>>(M, Mj, n1);

    final_kernel<<<1, 256>>>(nb_f, nb_w, (float*)d_out);
}

// round 8
// speedup vs baseline: 2.5979x; 1.0714x over previous
#include <cuda_runtime.h>

#define TPB 256

// d values (level 0)
__device__ __align__(16) float g_d[12000032];
// pyramid: A1 (tile sums) at [0, n1), A2->S2 at [n1, n1+n2)
__device__ __align__(16) float g_lvl[900032];
__device__ double g_thr_part[65536];
__device__ double g_win_part[65536];

__device__ __forceinline__ int sidx(int i) { return i + (i >> 4); }  // 17-stride pad

__device__ __forceinline__ float edge_len(float2 a, float2 b) {
    float dx = __fsub_rn(a.x, b.x);
    float dy = __fsub_rn(a.y, b.y);
    float s  = __fmaf_rn(dy, dy, __fmul_rn(dx, dx));
    return __fsqrt_rn(s);
}

__device__ __forceinline__ double block_reduce_double(double v, double* swarp) {
    int lane = threadIdx.x & 31, wid = threadIdx.x >> 5;
    #pragma unroll
    for (int o = 16; o > 0; o >>= 1) v += __shfl_down_sync(0xffffffffu, v, o);
    if (lane == 0) swarp[wid] = v;
    __syncthreads();
    double r = 0.0;
    if (wid == 0) {
        r = (lane < (blockDim.x >> 5)) ? swarp[lane] : 0.0;
        #pragma unroll
        for (int o = 4; o > 0; o >>= 1) r += __shfl_down_sync(0xffffffffu, r, o);
    }
    return r;  // valid in thread 0
}

// Kernel A: edges + threshold partial + A1 (48/block) + A2 (3/block).
// Block = 256 faces = 768 d values; 768 = 48*16, 48 = 3*16.
__global__ void edges_kernel(const float2* __restrict__ pts,
                             const int* __restrict__ faces, int F, int M,
                             long off2, int n1, int n2) {
    __shared__ float sd[816];          // 768 + 48 pad
    __shared__ float sA1[48];
    __shared__ int   sfaces[768];
    __shared__ double swarp[8];
    int tid = threadIdx.x;
    int B0 = blockIdx.x * TPB;
    long ibase = (long)B0 * 3;
    int totalInts = 3 * F;

    // Stage faces coalesced.
    if (ibase + 768 <= totalInts) {
        if (tid < 192) {
            const int4* f4 = reinterpret_cast<const int4*>(faces + ibase);
            reinterpret_cast<int4*>(sfaces)[tid] = f4[tid];
        }
    } else {
        for (int i = tid; i < 768; i += TPB)
            if (ibase + i < totalInts) sfaces[i] = faces[ibase + i];
    }
    __syncthreads();

    int f = B0 + tid;
    float facc = 0.0f;
    if (f < F) {
        int lb = 3 * tid;
        int i0 = sfaces[lb], i1 = sfaces[lb + 1], i2 = sfaces[lb + 2];
        float2 p0 = __ldg(&pts[i0]), p1 = __ldg(&pts[i1]), p2 = __ldg(&pts[i2]);
        float d0 = edge_len(p2, p0);
        float d1 = edge_len(p0, p1);
        float d2 = edge_len(p1, p2);
        sd[sidx(lb)] = d0; sd[sidx(lb + 1)] = d1; sd[sidx(lb + 2)] = d2;
        if (d0 < 7.0f) { float s = __fsub_rn(7.0f, d0); facc += __fmul_rn(s, s); }
        if (d1 < 7.0f) { float s = __fsub_rn(7.0f, d1); facc += __fmul_rn(s, s); }
        if (d2 < 7.0f) { float s = __fsub_rn(7.0f, d2); facc += __fmul_rn(s, s); }
    }
    __syncthreads();

    int gbase = B0 * 3;                // block's global d base (16-aligned)
    int lim = M - gbase;               // valid d count in this block
    // Coalesced d store from smem.
    #pragma unroll
    for (int k = 0; k < 3; k++) {
        int idx = tid + k * TPB;
        if (idx < lim) g_d[gbase + idx] = sd[sidx(idx)];
    }
    if (tid < 48) {
        // A1 tile sums: sequential RN adds in index order.
        float a = 0.0f;
        int lb = tid * 16;
        #pragma unroll
        for (int i = 0; i < 16; i++) {
            if (lb + i < lim) a = __fadd_rn(a, sd[sidx(lb + i)]);
        }
        sA1[tid] = a;
        int gt = blockIdx.x * 48 + tid;
        if (lb < lim && gt < n1) g_lvl[gt] = a;
    }
    __syncthreads();
    if (tid < 3) {
        int gt2 = blockIdx.x * 3 + tid;
        if (gt2 < n2) {
            int a1base = blockIdx.x * 48 + tid * 16;
            float a = 0.0f;
            #pragma unroll
            for (int i = 0; i < 16; i++) {
                if (a1base + i < n1) a = __fadd_rn(a, sA1[tid * 16 + i]);
            }
            if (a1base < n1) g_lvl[off2 + gt2] = a;
        }
    }
    double tot = block_reduce_double((double)facc, swarp);
    if (tid == 0) g_thr_part[blockIdx.x] = tot;
}

// Single-block kernel: A2 (gmem, n2) -> A3 -> A4 -> A5 (smem) -> seq scan ->
// S4 -> S3 -> S2 (gmem in place). Same add sequences as per-level kernels.
__global__ void fused_mid(long off2, int n2) {
    __shared__ float sA3[3072];
    __shared__ float sA4[256];
    __shared__ float sA5[16];
    int tid = threadIdx.x, nt = blockDim.x;
    int n3 = (n2 + 15) / 16;
    int n4 = (n3 + 15) / 16;
    int n5 = (n4 + 15) / 16;
    for (int t = tid; t < n3; t += nt) {
        float a = 0.0f;
        int base = t * 16, l = n2 - base; if (l > 16) l = 16;
        #pragma unroll
        for (int i = 0; i < 16; i++) if (i < l) a = __fadd_rn(a, g_lvl[off2 + base + i]);
        sA3[t] = a;
    }
    __syncthreads();
    for (int t = tid; t < n4; t += nt) {
        float a = 0.0f;
        int base = t * 16, l = n3 - base; if (l > 16) l = 16;
        #pragma unroll
        for (int i = 0; i < 16; i++) if (i < l) a = __fadd_rn(a, sA3[base + i]);
        sA4[t] = a;
    }
    __syncthreads();
    for (int t = tid; t < n5; t += nt) {
        float a = 0.0f;
        int base = t * 16, l = n4 - base; if (l > 16) l = 16;
        #pragma unroll
        for (int i = 0; i < 16; i++) if (i < l) a = __fadd_rn(a, sA4[base + i]);
        sA5[t] = a;
    }
    __syncthreads();
    if (tid == 0) {
        float acc = 0.0f;
        for (int i = 0; i < n5; i++) { acc = __fadd_rn(acc, sA5[i]); sA5[i] = acc; }
    }
    __syncthreads();
    for (int t = tid; t < n5; t += nt) {
        float off = (t > 0) ? sA5[t - 1] : 0.0f;
        int base = t * 16, l = n4 - base; if (l > 16) l = 16;
        float acc = 0.0f;
        #pragma unroll
        for (int i = 0; i < 16; i++) if (i < l) {
            acc = __fadd_rn(acc, sA4[base + i]);
            sA4[base + i] = __fadd_rn(off, acc);
        }
    }
    __syncthreads();
    for (int t = tid; t < n4; t += nt) {
        float off = (t > 0) ? sA4[t - 1] : 0.0f;
        int base = t * 16, l = n3 - base; if (l > 16) l = 16;
        float acc = 0.0f;
        #pragma unroll
        for (int i = 0; i < 16; i++) if (i < l) {
            acc = __fadd_rn(acc, sA3[base + i]);
            sA3[base + i] = __fadd_rn(off, acc);
        }
    }
    __syncthreads();
    for (int t = tid; t < n3; t += nt) {
        float off = (t > 0) ? sA3[t - 1] : 0.0f;
        int base = t * 16, l = n2 - base; if (l > 16) l = 16;
        float acc = 0.0f;
        #pragma unroll
        for (int i = 0; i < 16; i++) if (i < l) {
            acc = __fadd_rn(acc, g_lvl[off2 + base + i]);
            g_lvl[off2 + base + i] = __fadd_rn(off, acc);
        }
    }
}

// S1[k] reconstructed on the fly (bitwise = up1): p = k>>4,
// off = S2[p-1] (0 if p==0), acc = seq RN prefix of A1[16p..k], S1 = RN(off+acc).
__device__ __forceinline__ float s1_val(int k, long off2, int n1) {
    int p = k >> 4, r = k & 15;
    float off = (p > 0) ? g_lvl[off2 + p - 1] : 0.0f;
    float acc = 0.0f;
    int base = p * 16;
    #pragma unroll
    for (int i = 0; i < 16; i++) {
        if (i <= r && base + i < n1) acc = __fadd_rn(acc, g_lvl[base + i]);
    }
    return __fadd_rn(off, acc);
}

// Kernel B: reconstruct S0 per tile from d + (A1,S2), then windows.
__global__ void window_kernel(int M, int Mj, int nTiles, long off2) {
    __shared__ float s[4448];
    __shared__ double swarp[8];
    int tid = threadIdx.x;
    int T0 = blockIdx.x * TPB;
    int dstart = 16 * (T0 - 1);
    for (int idx = tid; idx < 258 * 16; idx += TPB) {
        int g = dstart + idx;
        float v = (g >= 0 && g < M) ? g_d[g] : 0.0f;
        s[sidx(idx)] = v;
    }
    __syncthreads();
    for (int lt = tid; lt < 258; lt += TPB) {
        int gt = T0 - 1 + lt;
        if (gt >= 0 && gt < nTiles) {
            float off = (gt > 0) ? s1_val(gt - 1, off2, nTiles) : 0.0f;
            float a = 0.0f;
            int lb = lt * 16;
            #pragma unroll
            for (int i = 0; i < 16; i++) {
                int p = sidx(lb + i);
                a = __fadd_rn(a, s[p]);
                s[p] = __fadd_rn(off, a);
            }
        }
    }
    __syncthreads();
    float facc = 0.0f;
    int gt = T0 + tid;
    if (gt < nTiles) {
        int lb = (tid + 1) * 16;
        #pragma unroll
        for (int i = 0; i < 16; i++) {
            int j = gt * 16 + i;
            if (j < Mj) {
                int lj = lb + i;
                float sj = s[sidx(lj)];
                float sn = s[sidx(lj + 5)];
                float lo = (j >= 5) ? s[sidx(lj - 5)] : 0.0f;
                float a = __fsub_rn(sj, lo);
                float b = __fsub_rn(sn, sj);
                float avg_prev;
                if (j >= 4) avg_prev = __fmul_rn(a, 0.2f);
                else        avg_prev = __fdiv_rn(a, (float)(j + 1));
                float avg_next = __fmul_rn(b, 0.2f);
                float diff = fabsf(__fsub_rn(avg_next, avg_prev));
                facc += __expf(diff);
            }
        }
    }
    double tot = block_reduce_double((double)facc, swarp);
    if (tid == 0) g_win_part[blockIdx.x] = tot;
}

__global__ void final_kernel(int np_thr, int np_win, float* __restrict__ out) {
    int tid = threadIdx.x;
    double s = 0.0;
    for (int i = tid; i < np_thr; i += 256) s += g_thr_part[i];
    for (int i = tid; i < np_win; i += 256) s += g_win_part[i];
    __shared__ double sh[256];
    sh[tid] = s;
    __syncthreads();
    for (int o = 128; o > 0; o >>= 1) {
        if (tid < o) sh[tid] += sh[tid + o];
        __syncthreads();
    }
    if (tid == 0) out[0] = (float)sh[0];
}

extern "C" void kernel_launch(void* const* d_in, const int* in_sizes, int n_in,
                              void* d_out, int out_size) {
    const float2* pts = (const float2*)d_in[0];
    const int* faces = (const int*)d_in[1];
    int M = in_sizes[1];      // 3 * F
    int F = M / 3;

    int n1 = (M + 15) / 16;
    int n2 = (n1 + 15) / 16;
    long off2 = n1;

    int nb_f = (F + TPB - 1) / TPB;
    edges_kernel<<<nb_f, TPB>>>(pts, faces, F, M, off2, n1, n2);

    fused_mid<<<1, 1024>>>(off2, n2);

    int Mj = M - 5;
    int nb_w = (n1 + TPB - 1) / TPB;
    window_kernel<<<nb_w, TPB>>>(M, Mj, n1, off2);

    final_kernel<<<1, 256>>>(nb_f, nb_w, (float*)d_out);
}